// round 17
// baseline (speedup 1.0000x reference)
#include <cuda_runtime.h>
#include <cuda_fp16.h>
#include <cstdint>
#include <cstddef>

// ---------------------------------------------------------------- constants
#define NB   4
#define NS_N 10000
#define NT_N 10000
#define NE   160000
#define NK   16
#define ND   128
#define M_NODES 40000
#define TILES_NODE 313
#define TILES_EDGE 5000
#define TILES_PER_BATCH 1250

#define NTHR 512
#define LDT 132     // C staging stride (floats)
#define LDH 136     // fp16 tile stride (halves)

// edge/proj SMEM (float offsets): A16[8704] BT[8704] C[64*132=8448]
#define EP_BT   8704
#define EP_C    17408
#define EP_FLOATS (EP_C + 64 * LDT)          // 25856 -> 103424 B  (2 CTAs/SM)
#define EP_BYTES (EP_FLOATS * 4)

// tgt SMEM: A16[8704] BT1[8704] BT2[8704] C[8448]
#define TG_BT1  8704
#define TG_BT2  17408
#define TG_C    26112
#define TG_FLOATS (TG_C + 64 * LDT)          // 34560 -> 138240 B  (1 CTA/SM)
#define TG_BYTES (TG_FLOATS * 4)

// ---------------------------------------------------------------- scratch
__device__ float g_Ps[(size_t)NB * NS_N * ND];
__device__ float g_Pt[(size_t)NB * NT_N * ND];
__device__ float g_dbond[(size_t)NB * NE * ND];
__device__ float g_bred[(size_t)NB * NT_N * ND];

// ---------------------------------------------------------------- helpers
__device__ __forceinline__ unsigned pk16(float lo, float hi) {
    unsigned r;
    asm("cvt.rn.f16x2.f32 %0, %1, %2;" : "=r"(r) : "f"(hi), "f"(lo));
    return r;
}
__device__ __forceinline__ void mma16(float c[4], const unsigned a[4], unsigned b0, unsigned b1) {
    asm volatile(
        "mma.sync.aligned.m16n8k16.row.col.f32.f16.f16.f32 "
        "{%0,%1,%2,%3},{%4,%5,%6,%7},{%8,%9},{%0,%1,%2,%3};"
        : "+f"(c[0]), "+f"(c[1]), "+f"(c[2]), "+f"(c[3])
        : "r"(a[0]), "r"(a[1]), "r"(a[2]), "r"(a[3]), "r"(b0), "r"(b1));
}
__device__ __forceinline__ void ldsm4(unsigned r[4], uint32_t addr) {
    asm volatile("ldmatrix.sync.aligned.m8n8.x4.shared.b16 {%0,%1,%2,%3}, [%4];"
                 : "=r"(r[0]), "=r"(r[1]), "=r"(r[2]), "=r"(r[3]) : "r"(addr));
}
__device__ __forceinline__ float silu_f(float x) { return x / (1.f + __expf(-x)); }

// Load fp32 tile from GMEM -> convert -> fp16 SMEM tile. Optional exact copy to copy_out.
__device__ __forceinline__ void load_conv_A16(void* A16, const float* __restrict__ Ag,
                                              size_t row0, size_t M, int tid,
                                              float* __restrict__ copy_out) {
    #pragma unroll
    for (int i = 0; i < 8; ++i) {
        int t = tid + i * NTHR;
        int r = t >> 5, c4 = (t & 31) << 2;
        size_t rr = row0 + (size_t)r;
        size_t rc = rr < M ? rr : (M - 1);
        float4 v = *(const float4*)(Ag + rc * ND + c4);
        uint2 o;
        o.x = pk16(v.x, v.y);
        o.y = pk16(v.z, v.w);
        *(uint2*)((char*)A16 + ((size_t)r * LDH + c4) * 2) = o;
        if (copy_out && rr < M)
            *(float4*)(copy_out + rr * ND + c4) = v;
    }
}

// BT16[n][k] = half(W[k][n])
__device__ __forceinline__ void stage_BT16(void* BTp, const float* __restrict__ W, int tid) {
    __half* p = (__half*)BTp;
    #pragma unroll
    for (int i = 0; i < 8; ++i) {
        int t = tid + i * NTHR;
        int k = t >> 5, c4 = (t & 31) << 2;
        float4 v = *(const float4*)(W + k * ND + c4);
        p[(c4 + 0) * LDH + k] = __float2half_rn(v.x);
        p[(c4 + 1) * LDH + k] = __float2half_rn(v.y);
        p[(c4 + 2) * LDH + k] = __float2half_rn(v.z);
        p[(c4 + 3) * LDH + k] = __float2half_rn(v.w);
    }
}

// 128x128x128 fp16 tile GEMM: 16 warps (4m x 4n), warp tile 32x32, dbl-buffered frags
__device__ __forceinline__ void tile_gemm16(uint32_t a0, uint32_t a1, uint32_t b0, uint32_t b1,
                                            float c[2][4][4]) {
    unsigned A[2][2][4], B[2][2][4];
#define LK(s, kb) do { \
    ldsm4(A[s][0], a0 + (kb)); \
    ldsm4(A[s][1], a1 + (kb)); \
    ldsm4(B[s][0], b0 + (kb)); \
    ldsm4(B[s][1], b1 + (kb)); } while (0)
    LK(0, 0);
    #pragma unroll
    for (int kk = 0; kk < 8; ++kk) {
        int s = kk & 1;
        if (kk < 7) {
            uint32_t kb = (uint32_t)(kk + 1) * 32u;   // 16 halves = 32 B
            if (s == 0) LK(1, kb); else LK(0, kb);
        }
        #pragma unroll
        for (int i = 0; i < 2; ++i)
            #pragma unroll
            for (int j = 0; j < 4; ++j)
                mma16(c[i][j], A[s][i], B[s][0][j], B[s][1][j]);
    }
#undef LK
}

__device__ __forceinline__ void zero_c(float c[2][4][4]) {
    #pragma unroll
    for (int i = 0; i < 2; ++i)
        #pragma unroll
        for (int j = 0; j < 4; ++j)
            c[i][j][0] = c[i][j][1] = c[i][j][2] = c[i][j][3] = 0.f;
}

// stage one 64-row pass of C: warps with (wm>>1)==p write rows (wm&1)*32 + ...
__device__ __forceinline__ void stage_pass64(float* Csh, float c[2][4][4], int p,
                                             int wm, int wn, int lr, int lc) {
    if ((wm >> 1) == p) {
        int rb = (wm & 1) * 32;
        #pragma unroll
        for (int i = 0; i < 2; ++i)
            #pragma unroll
            for (int j = 0; j < 4; ++j) {
                int rl = rb + i * 16 + lr;
                int col = wn * 32 + j * 8 + lc * 2;
                *(float2*)(Csh + rl * LDT + col)       = make_float2(c[i][j][0], c[i][j][1]);
                *(float2*)(Csh + (rl + 8) * LDT + col) = make_float2(c[i][j][2], c[i][j][3]);
            }
    }
}

// ---------------------------------------------------------------- K1: projections
// y==0: g_Ps = src @ Ws2e, out1 = src ; y==1: g_Pt = tgt @ Wt2e
__global__ __launch_bounds__(NTHR) void proj_kernel(const float* __restrict__ src,
                                                    const float* __restrict__ tgt,
                                                    const float* __restrict__ Ws,
                                                    const float* __restrict__ Wt,
                                                    float* __restrict__ out1) {
    extern __shared__ float sm[];
    float* Csh = sm + EP_C;
    int tid = threadIdx.x, lane = tid & 31, wid = tid >> 5;
    int wm = wid & 3, wn = wid >> 2;
    int lr = lane >> 2, lc = lane & 3;
    int cc = lane << 2;

    const float* Ag = blockIdx.y ? tgt : src;
    const float* Wg = blockIdx.y ? Wt : Ws;
    float* O = blockIdx.y ? g_Pt : g_Ps;
    float* copy_out = blockIdx.y ? nullptr : out1;

    stage_BT16(sm + EP_BT, Wg, tid);

    uint32_t smb = (uint32_t)__cvta_generic_to_shared(sm);
    int l15 = lane & 15, lk = (lane >> 4) * 8;
    uint32_t aoff0 = smb + (uint32_t)(((wm * 32 + l15) * LDH + lk) * 2);
    uint32_t aoff1 = aoff0 + (uint32_t)(16 * LDH * 2);
    uint32_t boff0 = smb + EP_BT * 4u + (uint32_t)(((wn * 32 + lane) * LDH) * 2);
    uint32_t boff1 = boff0 + 16u;

    for (int t = blockIdx.x; t < TILES_NODE; t += gridDim.x) {
        size_t row0 = (size_t)t * 128;
        load_conv_A16(sm, Ag, row0, (size_t)M_NODES, tid, copy_out);
        __syncthreads();

        float c[2][4][4];
        zero_c(c);
        tile_gemm16(aoff0, aoff1, boff0, boff1, c);

        #pragma unroll 1
        for (int p = 0; p < 2; ++p) {
            __syncthreads();
            stage_pass64(Csh, c, p, wm, wn, lr, lc);
            __syncthreads();
            #pragma unroll
            for (int rr = 0; rr < 4; ++rr) {
                int rl = wid * 4 + rr;
                size_t gr = row0 + (size_t)(p * 64 + rl);
                if (gr < (size_t)M_NODES)
                    *(float4*)(O + gr * ND + cc) = *(const float4*)(Csh + rl * LDT + cc);
            }
        }
        __syncthreads();   // C/A16 reuse guard
    }
}

// ---------------------------------------------------------------- K2: edge block
__global__ __launch_bounds__(NTHR) void edge_kernel(const float* __restrict__ bond,
                                                    const float* __restrict__ We2e,
                                                    const float* __restrict__ lng,
                                                    const float* __restrict__ lnb,
                                                    const int* __restrict__ so,
                                                    const int* __restrict__ to,
                                                    float* __restrict__ out0) {
    extern __shared__ float sm[];
    float* Csh = sm + EP_C;
    int tid = threadIdx.x, lane = tid & 31, wid = tid >> 5;
    int wm = wid & 3, wn = wid >> 2;
    int lr = lane >> 2, lc = lane & 3;
    int cc = lane << 2;

    stage_BT16(sm + EP_BT, We2e, tid);

    uint32_t smb = (uint32_t)__cvta_generic_to_shared(sm);
    int l15 = lane & 15, lk = (lane >> 4) * 8;
    uint32_t aoff0 = smb + (uint32_t)(((wm * 32 + l15) * LDH + lk) * 2);
    uint32_t aoff1 = aoff0 + (uint32_t)(16 * LDH * 2);
    uint32_t boff0 = smb + EP_BT * 4u + (uint32_t)(((wn * 32 + lane) * LDH) * 2);
    uint32_t boff1 = boff0 + 16u;

    float4 gg  = *(const float4*)(lng + cc);
    float4 bbv = *(const float4*)(lnb + cc);

    for (int t = blockIdx.x; t < TILES_EDGE; t += gridDim.x) {
        size_t row0 = (size_t)t * 128;
        load_conv_A16(sm, bond, row0, (size_t)NB * NE, tid, nullptr);
        __syncthreads();

        float c[2][4][4];
        zero_c(c);
        tile_gemm16(aoff0, aoff1, boff0, boff1, c);

        int b = t / TILES_PER_BATCH;
        int el0 = (t - b * TILES_PER_BATCH) * 128;
        const float* PsB = g_Ps + (size_t)b * NS_N * ND;
        const float* PtB = g_Pt + (size_t)b * NT_N * ND;

        #pragma unroll 1
        for (int p = 0; p < 2; ++p) {
            __syncthreads();
            stage_pass64(Csh, c, p, wm, wn, lr, lc);
            __syncthreads();
            #pragma unroll
            for (int rr = 0; rr < 4; ++rr) {
                int rl = wid * 4 + rr;
                int r = p * 64 + rl;
                int el = el0 + r;
                int si = __ldg(so + el);
                int ti = __ldg(to + el);
                float4 v  = *(const float4*)(Csh + rl * LDT + cc);
                float4 ps = *(const float4*)(PsB + (size_t)si * ND + cc);
                float4 pt = *(const float4*)(PtB + (size_t)ti * ND + cc);
                float x0 = silu_f(v.x + ps.x + pt.x);
                float x1 = silu_f(v.y + ps.y + pt.y);
                float x2 = silu_f(v.z + ps.z + pt.z);
                float x3 = silu_f(v.w + ps.w + pt.w);
                float s = x0 + x1 + x2 + x3;
                float q = x0 * x0 + x1 * x1 + x2 * x2 + x3 * x3;
                #pragma unroll
                for (int o = 16; o > 0; o >>= 1) {
                    s += __shfl_xor_sync(0xffffffffu, s, o);
                    q += __shfl_xor_sync(0xffffffffu, q, o);
                }
                float mean = s * (1.f / ND);
                float var  = q * (1.f / ND) - mean * mean;
                float rstd = rsqrtf(var + 1e-5f);
                float y0 = (x0 - mean) * rstd * gg.x + bbv.x;
                float y1 = (x1 - mean) * rstd * gg.y + bbv.y;
                float y2 = (x2 - mean) * rstd * gg.z + bbv.z;
                float y3 = (x3 - mean) * rstd * gg.w + bbv.w;
                size_t off = (row0 + (size_t)r) * ND + cc;
                float4 av = *(const float4*)(bond + off);   // exact fp32 bond (L2 hit)
                *(float4*)(g_dbond + off) = make_float4(y0, y1, y2, y3);
                *(float4*)(out0 + off) = make_float4(av.x + y0, av.y + y1, av.z + y2, av.w + y3);
            }
        }
        __syncthreads();
    }
}

// ---------------------------------------------------------------- K3: gather
__global__ __launch_bounds__(128) void gather_kernel(const int* __restrict__ edge_order,
                                                     const float* __restrict__ coef) {
    int bn = blockIdx.x;                 // 0 .. B*NT-1
    int b = bn / NT_N, nt = bn - b * NT_N;
    __shared__ int   eo[NK];
    __shared__ float cf[NK];
    if (threadIdx.x < NK) {
        eo[threadIdx.x] = edge_order[nt * NK + threadIdx.x];
        cf[threadIdx.x] = coef[nt * NK + threadIdx.x];
    }
    __syncthreads();
    int d = threadIdx.x;
    const float* base = g_dbond + (size_t)b * NE * ND;
    float acc = 0.f;
    #pragma unroll
    for (int k = 0; k < NK; ++k)
        acc += cf[k] * __ldg(base + (size_t)eo[k] * ND + d);
    g_bred[(size_t)bn * ND + d] = acc * (1.f / NK);
}

// ---------------------------------------------------------------- K4: fused tgt update
// out2 = tgt + LN(silu(bred@We2t + tgt@Wt2t))
__global__ __launch_bounds__(NTHR) void tgt_fused(const float* __restrict__ tgt,
                                                  const float* __restrict__ We2t,
                                                  const float* __restrict__ Wt2t,
                                                  const float* __restrict__ lng,
                                                  const float* __restrict__ lnb,
                                                  float* __restrict__ out2) {
    extern __shared__ float sm[];
    float* Csh = sm + TG_C;
    int tid = threadIdx.x, lane = tid & 31, wid = tid >> 5;
    int wm = wid & 3, wn = wid >> 2;
    int lr = lane >> 2, lc = lane & 3;
    int cc = lane << 2;

    stage_BT16(sm + TG_BT1, We2t, tid);
    stage_BT16(sm + TG_BT2, Wt2t, tid);

    uint32_t smb = (uint32_t)__cvta_generic_to_shared(sm);
    int l15 = lane & 15, lk = (lane >> 4) * 8;
    uint32_t aoff0 = smb + (uint32_t)(((wm * 32 + l15) * LDH + lk) * 2);
    uint32_t aoff1 = aoff0 + (uint32_t)(16 * LDH * 2);
    uint32_t b1off0 = smb + TG_BT1 * 4u + (uint32_t)(((wn * 32 + lane) * LDH) * 2);
    uint32_t b1off1 = b1off0 + 16u;
    uint32_t b2off0 = smb + TG_BT2 * 4u + (uint32_t)(((wn * 32 + lane) * LDH) * 2);
    uint32_t b2off1 = b2off0 + 16u;

    float4 gg  = *(const float4*)(lng + cc);
    float4 bbv = *(const float4*)(lnb + cc);

    for (int t = blockIdx.x; t < TILES_NODE; t += gridDim.x) {
        size_t row0 = (size_t)t * 128;

        load_conv_A16(sm, g_bred, row0, (size_t)M_NODES, tid, nullptr);
        __syncthreads();

        float c[2][4][4];
        zero_c(c);
        tile_gemm16(aoff0, aoff1, b1off0, b1off1, c);
        __syncthreads();                         // all warps done with bred A16

        load_conv_A16(sm, tgt, row0, (size_t)M_NODES, tid, nullptr);
        __syncthreads();

        tile_gemm16(aoff0, aoff1, b2off0, b2off1, c);

        #pragma unroll 1
        for (int p = 0; p < 2; ++p) {
            __syncthreads();
            stage_pass64(Csh, c, p, wm, wn, lr, lc);
            __syncthreads();
            #pragma unroll
            for (int rr = 0; rr < 4; ++rr) {
                int rl = wid * 4 + rr;
                int r = p * 64 + rl;
                size_t gr = row0 + (size_t)r;
                if (gr >= (size_t)M_NODES) continue;
                float4 v = *(const float4*)(Csh + rl * LDT + cc);
                float x0 = silu_f(v.x);
                float x1 = silu_f(v.y);
                float x2 = silu_f(v.z);
                float x3 = silu_f(v.w);
                float s = x0 + x1 + x2 + x3;
                float q = x0 * x0 + x1 * x1 + x2 * x2 + x3 * x3;
                #pragma unroll
                for (int o = 16; o > 0; o >>= 1) {
                    s += __shfl_xor_sync(0xffffffffu, s, o);
                    q += __shfl_xor_sync(0xffffffffu, q, o);
                }
                float mean = s * (1.f / ND);
                float var  = q * (1.f / ND) - mean * mean;
                float rstd = rsqrtf(var + 1e-5f);
                float y0 = (x0 - mean) * rstd * gg.x + bbv.x;
                float y1 = (x1 - mean) * rstd * gg.y + bbv.y;
                float y2 = (x2 - mean) * rstd * gg.z + bbv.z;
                float y3 = (x3 - mean) * rstd * gg.w + bbv.w;
                float4 av = *(const float4*)(tgt + gr * ND + cc);   // exact fp32 tgt (L2 hit)
                *(float4*)(out2 + gr * ND + cc) =
                    make_float4(av.x + y0, av.y + y1, av.z + y2, av.w + y3);
            }
        }
        __syncthreads();
    }
}

// ---------------------------------------------------------------- launch
extern "C" void kernel_launch(void* const* d_in, const int* in_sizes, int n_in,
                              void* d_out, int out_size) {
    const float* bond = (const float*)d_in[0];
    const float* src  = (const float*)d_in[1];
    const float* tgt  = (const float*)d_in[2];
    const float* Ws2e = (const float*)d_in[3];
    const float* Wt2e = (const float*)d_in[4];
    const float* We2e = (const float*)d_in[5];
    const float* ln1g = (const float*)d_in[6];
    const float* ln1b = (const float*)d_in[7];
    const float* We2t = (const float*)d_in[8];
    const float* Wt2t = (const float*)d_in[9];
    const float* ln2g = (const float*)d_in[10];
    const float* ln2b = (const float*)d_in[11];
    const float* coef = (const float*)d_in[12];
    const int* so = (const int*)d_in[13];
    const int* to = (const int*)d_in[14];
    const int* eo = (const int*)d_in[15];

    float* out0 = (float*)d_out;                     // [B,E,D]
    float* out1 = out0 + (size_t)NB * NE * ND;       // [B,NS,D]
    float* out2 = out1 + (size_t)NB * NS_N * ND;     // [B,NT,D]

    cudaFuncSetAttribute(proj_kernel, cudaFuncAttributeMaxDynamicSharedMemorySize, EP_BYTES);
    cudaFuncSetAttribute(edge_kernel, cudaFuncAttributeMaxDynamicSharedMemorySize, EP_BYTES);
    cudaFuncSetAttribute(tgt_fused,   cudaFuncAttributeMaxDynamicSharedMemorySize, TG_BYTES);

    // P_s = src@Ws2e (+ out1=src), P_t = tgt@Wt2e — 296 CTAs, 2/SM
    proj_kernel<<<dim3(148, 2), NTHR, EP_BYTES>>>(src, tgt, Ws2e, Wt2e, out1);
    // edge block — 296 CTAs, 2/SM
    edge_kernel<<<296, NTHR, EP_BYTES>>>(bond, We2e, ln1g, ln1b, so, to, out0);
    // bond -> node weighted mean
    gather_kernel<<<NB * NT_N, 128>>>(eo, coef);
    // out2 = tgt + LN(silu(bred@We2t + tgt@Wt2t)) — 148 CTAs
    tgt_fused<<<148, NTHR, TG_BYTES>>>(tgt, We2t, Wt2t, ln2g, ln2b, out2);
}